// round 16
// baseline (speedup 1.0000x reference)
#include <cuda_runtime.h>
#include <cuda_fp16.h>
#include <math.h>
#include <stdint.h>

typedef __half H;

// Problem constants: B=16, QL=VL=512, HID=1024, NH=4, DIM=256, CH=10
#define SZ_ACT (8192 * 1024)
#define SZ_ATT (64 * 512 * 512)

// GEMM modes
#define TSC    4
#define TCTX   5
#define TTANH  6
#define TBIG   7
#define TFOLDA 8

// Dynamic SMEM: 4 stages x (A 128x40 + B 128x40) halves (32-wide K chunks)
#define BOFF    10240
#define STGB    20480
#define SMEMDYN (4 * STGB)

// ------------------------- device scratch ------------------------------------
__device__ float dW2[768], dB2[256], dW2k[768], dW2v[768], dCk[1024], dCv[1024], dBq2[1024];
__device__ float dATTN[SZ_ATT];

__device__ __align__(256) H g_q[SZ_ACT];
__device__ __align__(256) H g_v[SZ_ACT];
__device__ __align__(256) H g_Wq[1048576];
__device__ __align__(256) H g_Wv[1048576];
__device__ __align__(256) H g_sqT[65536];
__device__ __align__(256) H g_skT[65536];
__device__ __align__(256) H g_svT[65536];
__device__ __align__(256) H g_WoT[2097152];
__device__ __align__(256) H g_Wq2T[1048576];
__device__ __align__(256) H g_WvkT[1048576];
__device__ __align__(256) H g_WvvT[1048576];
__device__ __align__(256) H g_qq[SZ_ACT];
__device__ __align__(256) H g_kk[SZ_ACT];
__device__ __align__(256) H g_vv[SZ_ACT];
__device__ __align__(256) H g_vvT[SZ_ACT];
__device__ __align__(256) H g_at[SZ_ATT];
__device__ __align__(256) H g_cx[SZ_ACT];

// ------------------------- helpers -------------------------------------------
__device__ __forceinline__ uint32_t smem_u32(const void* p) {
    uint32_t a;
    asm("{ .reg .u64 t; cvta.to.shared.u64 t, %1; cvt.u32.u64 %0, t; }" : "=r"(a) : "l"(p));
    return a;
}

#define LDSM4(r0, r1, r2, r3, a) \
    asm volatile("ldmatrix.sync.aligned.m8n8.x4.shared.b16 {%0,%1,%2,%3}, [%4];" \
        : "=r"(r0), "=r"(r1), "=r"(r2), "=r"(r3) : "r"(a))
#define MMA16816(c, a, b) \
    asm volatile("mma.sync.aligned.m16n8k16.row.col.f32.f16.f16.f32 " \
        "{%0,%1,%2,%3}, {%4,%5,%6,%7}, {%8,%9}, {%0,%1,%2,%3};" \
        : "+f"((c)[0]), "+f"((c)[1]), "+f"((c)[2]), "+f"((c)[3]) \
        : "r"((a)[0]), "r"((a)[1]), "r"((a)[2]), "r"((a)[3]), "r"((b)[0]), "r"((b)[1]))
#define CPA16(sa, ga) \
    asm volatile("cp.async.cg.shared.global [%0], [%1], 16;" :: "r"(sa), "l"(ga))
#define CPCOMMIT() asm volatile("cp.async.commit_group;" ::: "memory")
#define CPWAIT0()  asm volatile("cp.async.wait_group 0;" ::: "memory")
#define CPWAIT1()  asm volatile("cp.async.wait_group 1;" ::: "memory")
#define CPWAIT2()  asm volatile("cp.async.wait_group 2;" ::: "memory")

// ------------------------- tiny precompute -----------------------------------
__global__ void prep1(const float* __restrict__ cw, const float* __restrict__ cb,
                      const float* __restrict__ Wloc) {
    int d = threadIdx.x;  // 256
    float w0 = 0.f, w1 = 0.f, w2 = 0.f, b2 = 0.f;
    for (int c = 0; c < 10; c++) {
        float wl = Wloc[c * 256 + d];
        w0 += cw[c * 3 + 0] * wl; w1 += cw[c * 3 + 1] * wl; w2 += cw[c * 3 + 2] * wl;
        b2 += cb[c] * wl;
    }
    dW2[d] = w0; dW2[256 + d] = w1; dW2[512 + d] = w2; dB2[d] = b2;
}

__global__ void prep2(const float* __restrict__ swq, const float* __restrict__ sbq,
                      const float* __restrict__ swk, const float* __restrict__ sbk,
                      const float* __restrict__ swv, const float* __restrict__ sbv,
                      const float* __restrict__ bias, const float* __restrict__ bq) {
    int idx = blockIdx.x * 256 + threadIdx.x;
    if (idx < 768) {
        int k = idx >> 8, d = idx & 255; float s = 0.f;
        for (int e = 0; e < 256; e++) s += dW2[k * 256 + e] * swk[e * 256 + d];
        dW2k[idx] = s;
    } else if (idx < 1536) {
        int t = idx - 768; int k = t >> 8, d = t & 255; float s = 0.f;
        for (int e = 0; e < 256; e++) s += dW2[k * 256 + e] * swv[e * 256 + d];
        dW2v[t] = s;
    } else if (idx < 2560) {
        int t = idx - 1536; int h = t >> 8, d = t & 255; float s = sbk[d];
        for (int e = 0; e < 256; e++) s += (bias[h * 256 + e] + dB2[e]) * swk[e * 256 + d];
        dCk[t] = s;
    } else if (idx < 3584) {
        int t = idx - 2560; int h = t >> 8, d = t & 255; float s = sbv[d];
        for (int e = 0; e < 256; e++) s += (bias[h * 256 + e] + dB2[e]) * swv[e * 256 + d];
        dCv[t] = s;
    } else if (idx < 4608) {
        int t = idx - 3584; int h = t >> 8, d = t & 255; float s = sbq[d];
        for (int e = 0; e < 256; e++) s += bq[h * 256 + e] * swq[e * 256 + d];
        dBq2[t] = s;
    }
}

// ------------------------- convert / transpose -------------------------------
__global__ void cvtKn(const float4* __restrict__ s, __half2* __restrict__ o, int n4) {
    int i = blockIdx.x * 256 + threadIdx.x;
    if (i >= n4) return;
    float4 v = s[i];
    o[i * 2 + 0] = __floats2half2_rn(v.x, v.y);
    o[i * 2 + 1] = __floats2half2_rn(v.z, v.w);
}

// out[c][r] = src[r][c]; src R x C row-major, out C x R
__global__ void cvtT(const float* __restrict__ s, H* __restrict__ o, int R, int C) {
    __shared__ float t[32][33];
    int r0 = blockIdx.y * 32, c0 = blockIdx.x * 32;
    int tx = threadIdx.x & 31, ty = threadIdx.x >> 5;
    for (int y = ty; y < 32; y += 8) t[y][tx] = s[(size_t)(r0 + y) * C + c0 + tx];
    __syncthreads();
    for (int y = ty; y < 32; y += 8)
        o[(size_t)(c0 + y) * R + r0 + tx] = __float2half(t[tx][y]);
}

// three 256x256 transposes in one launch (z selects matrix)
__global__ void cvtT3(const float* __restrict__ s0, const float* __restrict__ s1,
                      const float* __restrict__ s2) {
    __shared__ float t[32][33];
    const float* s = (blockIdx.z == 0) ? s0 : (blockIdx.z == 1) ? s1 : s2;
    H* o = (blockIdx.z == 0) ? g_sqT : (blockIdx.z == 1) ? g_skT : g_svT;
    int r0 = blockIdx.y * 32, c0 = blockIdx.x * 32;
    int tx = threadIdx.x & 31, ty = threadIdx.x >> 5;
    for (int y = ty; y < 32; y += 8) t[y][tx] = s[(size_t)(r0 + y) * 256 + c0 + tx];
    __syncthreads();
    for (int y = ty; y < 32; y += 8)
        o[(size_t)(c0 + y) * 256 + r0 + tx] = __float2half(t[tx][y]);
}

// vv [(b*512+l)*1024 + h*256+d] -> vvT [((h*16+b)*256+d)*512 + l]
__global__ void transVV(const H* __restrict__ s, H* __restrict__ o) {
    __shared__ H t0[32][33];
    int l0 = blockIdx.x * 32, d0 = blockIdx.y * 32;
    int z = blockIdx.z, h = z >> 4, b = z & 15;
    int tx = threadIdx.x & 31, ty = threadIdx.x >> 5;
    for (int y = ty; y < 32; y += 8)
        t0[y][tx] = s[(size_t)(b * 512 + l0 + y) * 1024 + h * 256 + d0 + tx];
    __syncthreads();
    for (int y = ty; y < 32; y += 8)
        o[(size_t)(z * 256 + d0 + y) * 512 + l0 + tx] = t0[tx][y];
}

// ------------------------- softmax row-512 + fp16 emit -----------------------
__global__ void softmax512(float* __restrict__ a, __half2* __restrict__ ho) {
    float* p = a + (size_t)blockIdx.x * 512;
    int t = threadIdx.x;  // 128
    float4 v = *(float4*)&p[t * 4];
    float m = fmaxf(fmaxf(v.x, v.y), fmaxf(v.z, v.w));
#pragma unroll
    for (int o = 16; o > 0; o >>= 1) m = fmaxf(m, __shfl_xor_sync(0xffffffffu, m, o));
    __shared__ float sh[4], sh2[4];
    int w = t >> 5, lane = t & 31;
    if (lane == 0) sh[w] = m;
    __syncthreads();
    m = fmaxf(fmaxf(sh[0], sh[1]), fmaxf(sh[2], sh[3]));
    v.x = __expf(v.x - m); v.y = __expf(v.y - m); v.z = __expf(v.z - m); v.w = __expf(v.w - m);
    float s = v.x + v.y + v.z + v.w;
#pragma unroll
    for (int o = 16; o > 0; o >>= 1) s += __shfl_xor_sync(0xffffffffu, s, o);
    if (lane == 0) sh2[w] = s;
    __syncthreads();
    s = sh2[0] + sh2[1] + sh2[2] + sh2[3];
    float inv = 1.f / s;
    v.x *= inv; v.y *= inv; v.z *= inv; v.w *= inv;
    *(float4*)&p[t * 4] = v;
    size_t base = (size_t)blockIdx.x * 256 + t * 2;
    ho[base + 0] = __floats2half2_rn(v.x, v.y);
    ho[base + 1] = __floats2half2_rn(v.z, v.w);
}

// ------------------------- mma.sync fp16 GEMM, tile 128x128 ------------------
// 4 warps as 2x2, warp tile 64x64; 32-wide K-chunks; 4-stage cp.async; occ 2.
// One __syncthreads per chunk; B fragments via pairwise ldmatrix.x4.
// TBIG merges qq/kk/vv (z selects); TFOLDA merges the 3 weight folds.
template <int MODE>
__global__ __launch_bounds__(128, 2)
void gemmTC(const H* __restrict__ Ah, const H* __restrict__ A2h,
            const H* __restrict__ Bh,
            H* __restrict__ Ch, float* __restrict__ Cf,
            int K, int lda, int ldb, int ldc,
            const float* __restrict__ bias, const float* __restrict__ pa) {
    extern __shared__ H smem[];
    const int tid = threadIdx.x;
    const int lane = tid & 31, wid = tid >> 5;
    const int wm = (wid >> 1) * 64, wn = (wid & 1) * 64;
    const int bm = blockIdx.y * 128, bn = blockIdx.x * 128;
    const int z = blockIdx.z;
    int which = 0;

    if (MODE == TBIG) {
        which = z;                       // 0=qq 1=kk 2=vv
        Ah = which ? g_v : g_q;
        Bh = (which == 0) ? g_Wq2T : (which == 1) ? g_WvkT : g_WvvT;
        Ch = (which == 0) ? g_qq : (which == 1) ? g_kk : g_vv;
    }
    if (MODE == TFOLDA) {
        int head = z & 3; which = z >> 2;
        Ah = (which == 0) ? g_sqT : (which == 1) ? g_skT : g_svT;
        Bh = ((which == 0) ? g_Wq : g_Wv) + head * 256;
        Ch = ((which == 0) ? g_Wq2T : (which == 1) ? g_WvkT : g_WvvT) +
             (size_t)head * 256 * 1024;
    }
    if (MODE == TSC) {
        int h = z >> 4, b = z & 15;
        size_t o = (size_t)b * 512 * 1024 + h * 256;
        Ah += o; Bh += o;
        Cf += (size_t)z * 262144;
    }
    if (MODE == TCTX) {
        int h = z >> 4, b = z & 15;
        Ah += (size_t)z * 262144;
        Bh += (size_t)z * 131072;
        Ch += (size_t)b * 512 * 1024 + h * 256;
    }

    float acc[4][8][4];
#pragma unroll
    for (int a = 0; a < 4; a++)
#pragma unroll
        for (int b = 0; b < 8; b++)
#pragma unroll
            for (int c = 0; c < 4; c++) acc[a][b][c] = 0.f;

    const int NC = K >> 5;  // 32-wide K-chunks
    uint32_t sbase = smem_u32(smem);

    const int rowL = tid >> 2;          // 0..31
    const int segL = (tid & 3) * 8;     // half offset within 32-half row

#define ISSUE(c_) do {                                                             \
    int k0 = (c_) << 5;                                                            \
    const H* ah = Ah; int ka = k0;                                                 \
    if (MODE == TTANH && k0 >= 1024) { ah = A2h; ka = k0 - 1024; }                 \
    uint32_t st = sbase + ((c_) & 3) * STGB;                                       \
    uint32_t so = st + (rowL * 40 + segL) * 2;                                     \
    CPA16(so,        ah + (size_t)(bm + rowL) * lda + ka + segL);                  \
    CPA16(so + 2560, ah + (size_t)(bm + rowL + 32) * lda + ka + segL);             \
    CPA16(so + 5120, ah + (size_t)(bm + rowL + 64) * lda + ka + segL);             \
    CPA16(so + 7680, ah + (size_t)(bm + rowL + 96) * lda + ka + segL);             \
    uint32_t sb = st + BOFF + (rowL * 40 + segL) * 2;                              \
    CPA16(sb,        Bh + (size_t)(bn + rowL) * ldb + k0 + segL);                  \
    CPA16(sb + 2560, Bh + (size_t)(bn + rowL + 32) * ldb + k0 + segL);             \
    CPA16(sb + 5120, Bh + (size_t)(bn + rowL + 64) * ldb + k0 + segL);             \
    CPA16(sb + 7680, Bh + (size_t)(bn + rowL + 96) * ldb + k0 + segL);             \
    CPCOMMIT();                                                                    \
} while (0)

    const int la15 = lane & 15;
    const int laHi = (lane >> 4) << 3;
    const int broff = ((lane >> 4) << 3) + (lane & 7);   // B x4 row offset
    const int bcoff = ((lane >> 3) & 1) << 3;            // B x4 col offset

    ISSUE(0); ISSUE(1); ISSUE(2);
    for (int c = 0; c < NC; c++) {
        int rem = NC - 1 - c;
        if (rem >= 2) { CPWAIT2(); } else if (rem == 1) { CPWAIT1(); } else { CPWAIT0(); }
        __syncthreads();
        if (c + 3 < NC) ISSUE(c + 3);
        uint32_t st = sbase + (c & 3) * STGB;
#pragma unroll
        for (int kk = 0; kk < 2; kk++) {
            uint32_t af[4][4], bh[8][2];
#pragma unroll
            for (int mt = 0; mt < 4; mt++) {
                uint32_t addr = st + ((wm + mt * 16 + la15) * 40 + kk * 16 + laHi) * 2;
                LDSM4(af[mt][0], af[mt][1], af[mt][2], af[mt][3], addr);
            }
#pragma unroll
            for (int np = 0; np < 4; np++) {
                uint32_t addr = st + BOFF +
                    ((wn + np * 16 + broff) * 40 + kk * 16 + bcoff) * 2;
                LDSM4(bh[2 * np][0], bh[2 * np][1], bh[2 * np + 1][0], bh[2 * np + 1][1], addr);
            }
#pragma unroll
            for (int mt = 0; mt < 4; mt++)
#pragma unroll
                for (int nt = 0; nt < 8; nt++)
                    MMA16816(acc[mt][nt], af[mt], bh[nt]);
        }
    }
#undef ISSUE

    // ------------- epilogue: fused math + fp16 emit, straight from regs ------
    const bool doKV = (MODE == TBIG) && (which != 0);
    const float* W2x = (which == 1) ? dW2k : dW2v;
    const float* cxp = (which == 1) ? dCk : dCv;
#pragma unroll
    for (int mt = 0; mt < 4; mt++) {
        int r0g = bm + wm + mt * 16 + (lane >> 2);
        int r1g = r0g + 8;
        float p0a = 0.f, p1a = 0.f, p2a = 0.f, p0b = 0.f, p1b = 0.f, p2b = 0.f;
        if (MODE == TBIG) {
            if (doKV) {
                int hh = (bn + wn) >> 8;   // 64-wide warp col inside one head
                {
                    int b = r0g >> 9, l = r0g & 511;
                    size_t pb = (size_t)(b * 4 + hh) * 512;
                    p0a = (l >= 1)   ? pa[pb + l - 1] : 0.f;
                    p1a =              pa[pb + l];
                    p2a = (l <= 510) ? pa[pb + l + 1] : 0.f;
                }
                {
                    int b = r1g >> 9, l = r1g & 511;
                    size_t pb = (size_t)(b * 4 + hh) * 512;
                    p0b = (l >= 1)   ? pa[pb + l - 1] : 0.f;
                    p1b =              pa[pb + l];
                    p2b = (l <= 510) ? pa[pb + l + 1] : 0.f;
                }
            }
        }
#pragma unroll
        for (int nt = 0; nt < 8; nt++) {
            int cc = bn + wn + nt * 8 + (lane & 3) * 2;
            float v00 = acc[mt][nt][0], v01 = acc[mt][nt][1];
            float v10 = acc[mt][nt][2], v11 = acc[mt][nt][3];
            if (MODE == TBIG) {
                if (which == 0) {
                    float b0 = dBq2[cc], b1 = dBq2[cc + 1];
                    v00 += b0; v01 += b1; v10 += b0; v11 += b1;
                } else {
                    int d0 = cc & 255, d1 = d0 + 1;
                    float c0 = cxp[cc], c1 = cxp[cc + 1];
                    float w00 = W2x[d0], w10 = W2x[256 + d0], w20 = W2x[512 + d0];
                    float w01 = W2x[d1], w11 = W2x[256 + d1], w21 = W2x[512 + d1];
                    v00 += c0 + p0a * w00 + p1a * w10 + p2a * w20;
                    v01 += c1 + p0a * w01 + p1a * w11 + p2a * w21;
                    v10 += c0 + p0b * w00 + p1b * w10 + p2b * w20;
                    v11 += c1 + p0b * w01 + p1b * w11 + p2b * w21;
                }
            }
            if (MODE == TSC) { v00 *= 0.0625f; v01 *= 0.0625f; v10 *= 0.0625f; v11 *= 0.0625f; }
            if (MODE == TTANH) {
                float b0 = bias[cc], b1 = bias[cc + 1];
                v00 = tanhf(v00 + b0); v01 = tanhf(v01 + b1);
                v10 = tanhf(v10 + b0); v11 = tanhf(v11 + b1);
            }
            if (MODE == TSC || MODE == TTANH) {
                *(float2*)&Cf[(size_t)r0g * ldc + cc] = make_float2(v00, v01);
                *(float2*)&Cf[(size_t)r1g * ldc + cc] = make_float2(v10, v11);
            } else {
                *(__half2*)(Ch + (size_t)r0g * ldc + cc) = __floats2half2_rn(v00, v01);
                *(__half2*)(Ch + (size_t)r1g * ldc + cc) = __floats2half2_rn(v10, v11);
            }
        }
    }
}

// ------------------------- launch --------------------------------------------
extern "C" void kernel_launch(void* const* d_in, const int* in_sizes, int n_in,
                              void* d_out, int out_size) {
    const float* query = (const float*)d_in[0];
    const float* value = (const float*)d_in[1];
    const float* pa    = (const float*)d_in[2];
    const float* cw    = (const float*)d_in[3];
    const float* cb    = (const float*)d_in[4];
    const float* Wq    = (const float*)d_in[5];
    const float* bq    = (const float*)d_in[6];
    const float* Wv    = (const float*)d_in[7];
    const float* Wloc  = (const float*)d_in[8];
    const float* bias  = (const float*)d_in[9];
    const float* Wout  = (const float*)d_in[10];
    const float* bout  = (const float*)d_in[11];
    const float* swq   = (const float*)d_in[12];
    const float* sbq   = (const float*)d_in[13];
    const float* swk   = (const float*)d_in[14];
    const float* sbk   = (const float*)d_in[15];
    const float* swv   = (const float*)d_in[16];
    const float* sbv   = (const float*)d_in[17];

    float* out = (float*)d_out;
    const size_t OUT_ELEMS  = (size_t)16 * 512 * 1024;
    const size_t ATTN_ELEMS = (size_t)64 * 512 * 512;

    float* pATT;
    cudaGetSymbolAddress((void**)&pATT, dATTN);
#define GETH(p, sym) H* p; cudaGetSymbolAddress((void**)&p, sym)
    GETH(qh, g_q);       GETH(vh, g_v);
    GETH(Wqh, g_Wq);     GETH(Wvh, g_Wv);
    GETH(WoT, g_WoT);
    GETH(qq, g_qq);      GETH(kk, g_kk);      GETH(vv, g_vv);
    GETH(vvT, g_vvT);    GETH(at, g_at);      GETH(cx, g_cx);
#undef GETH

    float* attn = ((size_t)out_size >= OUT_ELEMS + ATTN_ELEMS) ? (out + OUT_ELEMS) : pATT;

    // Not stream ops; deterministic on every call (no static guards allowed).
    cudaFuncSetAttribute(gemmTC<TFOLDA>, cudaFuncAttributeMaxDynamicSharedMemorySize, SMEMDYN);
    cudaFuncSetAttribute(gemmTC<TBIG>,   cudaFuncAttributeMaxDynamicSharedMemorySize, SMEMDYN);
    cudaFuncSetAttribute(gemmTC<TSC>,    cudaFuncAttributeMaxDynamicSharedMemorySize, SMEMDYN);
    cudaFuncSetAttribute(gemmTC<TCTX>,   cudaFuncAttributeMaxDynamicSharedMemorySize, SMEMDYN);
    cudaFuncSetAttribute(gemmTC<TTANH>,  cudaFuncAttributeMaxDynamicSharedMemorySize, SMEMDYN);

    dim3 T(128);
    // precompute + fp16 converts
    prep1<<<1, 256>>>(cw, cb, Wloc);
    prep2<<<18, 256>>>(swq, sbq, swk, sbk, swv, sbv, bias, bq);
    cvtKn<<<8192, 256>>>((const float4*)query, (__half2*)qh, 2097152);
    cvtKn<<<8192, 256>>>((const float4*)value, (__half2*)vh, 2097152);
    cvtKn<<<1024, 256>>>((const float4*)Wq, (__half2*)Wqh, 262144);
    cvtKn<<<1024, 256>>>((const float4*)Wv, (__half2*)Wvh, 262144);
    cvtT3<<<dim3(8, 8, 3), 256>>>(swq, swk, swv);
    cvtT<<<dim3(32, 64), 256>>>(Wout, WoT, 2048, 1024);

    // weight folds, all 12 tiles in one launch (z: head = z&3, which = z>>2)
    gemmTC<TFOLDA><<<dim3(8, 2, 12), T, SMEMDYN>>>(0, 0, 0,
        0, 0, 256, 256, 1024, 1024, 0, 0);

    // qq / kk / vv in one launch (z selects), fused epilogues emit fp16
    gemmTC<TBIG><<<dim3(8, 64, 3), T, SMEMDYN>>>(0, 0, 0,
        0, 0, 1024, 1024, 1024, 1024, 0, pa);
    transVV<<<dim3(16, 8, 64), 256>>>(vv, vvT);

    // attention
    gemmTC<TSC><<<dim3(4, 4, 64), T, SMEMDYN>>>(qq, 0, kk,
        0, attn, 256, 1024, 1024, 512, 0, 0);
    softmax512<<<64 * 512, 128>>>(attn, (__half2*)at);
    gemmTC<TCTX><<<dim3(2, 4, 64), T, SMEMDYN>>>(at, 0, vvT,
        cx, 0, 512, 512, 512, 1024, 0, 0);

    // out = tanh([ctx, query] @ Wout + bout)
    gemmTC<TTANH><<<dim3(8, 64, 1), T, SMEMDYN>>>(cx, qh, WoT,
        0, out, 2048, 1024, 2048, 1024, bout, 0);
}

// round 17
// speedup vs baseline: 1.0050x; 1.0050x over previous
#include <cuda_runtime.h>
#include <cuda_fp16.h>
#include <math.h>
#include <stdint.h>

typedef __half H;

// Problem constants: B=16, QL=VL=512, HID=1024, NH=4, DIM=256, CH=10
#define SZ_ACT (8192 * 1024)
#define SZ_ATT (64 * 512 * 512)

// GEMM modes
#define TSC    4
#define TCTX   5
#define TTANH  6
#define TBIG   7
#define TFOLDA 8

// Dynamic SMEM: 4 stages x (A 128x40 + B 128x40) halves (32-wide K chunks)
#define BOFF    10240
#define STGB    20480
#define SMEMDYN (4 * STGB)

// ------------------------- device scratch ------------------------------------
__device__ float dW2[768], dB2[256], dW2k[768], dW2v[768], dCk[1024], dCv[1024], dBq2[1024];
__device__ float dATTN[SZ_ATT];

__device__ __align__(256) H g_q[SZ_ACT];
__device__ __align__(256) H g_v[SZ_ACT];
__device__ __align__(256) H g_Wq[1048576];
__device__ __align__(256) H g_Wv[1048576];
__device__ __align__(256) H g_sqT[65536];
__device__ __align__(256) H g_skT[65536];
__device__ __align__(256) H g_svT[65536];
__device__ __align__(256) H g_WoT[2097152];
__device__ __align__(256) H g_Wq2T[1048576];
__device__ __align__(256) H g_WvkT[1048576];
__device__ __align__(256) H g_WvvT[1048576];
__device__ __align__(256) H g_qq[SZ_ACT];
__device__ __align__(256) H g_kk[SZ_ACT];
__device__ __align__(256) H g_vv[SZ_ACT];
__device__ __align__(256) H g_vvT[SZ_ACT];
__device__ __align__(256) H g_sc[SZ_ATT];   // raw fp16 scores (pre-softmax)
__device__ __align__(256) H g_at[SZ_ATT];   // fp16 post-softmax attn
__device__ __align__(256) H g_cx[SZ_ACT];

// ------------------------- helpers -------------------------------------------
__device__ __forceinline__ uint32_t smem_u32(const void* p) {
    uint32_t a;
    asm("{ .reg .u64 t; cvta.to.shared.u64 t, %1; cvt.u32.u64 %0, t; }" : "=r"(a) : "l"(p));
    return a;
}

#define LDSM4(r0, r1, r2, r3, a) \
    asm volatile("ldmatrix.sync.aligned.m8n8.x4.shared.b16 {%0,%1,%2,%3}, [%4];" \
        : "=r"(r0), "=r"(r1), "=r"(r2), "=r"(r3) : "r"(a))
#define MMA16816(c, a, b) \
    asm volatile("mma.sync.aligned.m16n8k16.row.col.f32.f16.f16.f32 " \
        "{%0,%1,%2,%3}, {%4,%5,%6,%7}, {%8,%9}, {%0,%1,%2,%3};" \
        : "+f"((c)[0]), "+f"((c)[1]), "+f"((c)[2]), "+f"((c)[3]) \
        : "r"((a)[0]), "r"((a)[1]), "r"((a)[2]), "r"((a)[3]), "r"((b)[0]), "r"((b)[1]))
#define CPA16(sa, ga) \
    asm volatile("cp.async.cg.shared.global [%0], [%1], 16;" :: "r"(sa), "l"(ga))
#define CPCOMMIT() asm volatile("cp.async.commit_group;" ::: "memory")
#define CPWAIT0()  asm volatile("cp.async.wait_group 0;" ::: "memory")
#define CPWAIT1()  asm volatile("cp.async.wait_group 1;" ::: "memory")
#define CPWAIT2()  asm volatile("cp.async.wait_group 2;" ::: "memory")

// ------------------------- tiny precompute -----------------------------------
__global__ void prep1(const float* __restrict__ cw, const float* __restrict__ cb,
                      const float* __restrict__ Wloc) {
    int d = threadIdx.x;  // 256
    float w0 = 0.f, w1 = 0.f, w2 = 0.f, b2 = 0.f;
    for (int c = 0; c < 10; c++) {
        float wl = Wloc[c * 256 + d];
        w0 += cw[c * 3 + 0] * wl; w1 += cw[c * 3 + 1] * wl; w2 += cw[c * 3 + 2] * wl;
        b2 += cb[c] * wl;
    }
    dW2[d] = w0; dW2[256 + d] = w1; dW2[512 + d] = w2; dB2[d] = b2;
}

__global__ void prep2(const float* __restrict__ swq, const float* __restrict__ sbq,
                      const float* __restrict__ swk, const float* __restrict__ sbk,
                      const float* __restrict__ swv, const float* __restrict__ sbv,
                      const float* __restrict__ bias, const float* __restrict__ bq) {
    int idx = blockIdx.x * 256 + threadIdx.x;
    if (idx < 768) {
        int k = idx >> 8, d = idx & 255; float s = 0.f;
        for (int e = 0; e < 256; e++) s += dW2[k * 256 + e] * swk[e * 256 + d];
        dW2k[idx] = s;
    } else if (idx < 1536) {
        int t = idx - 768; int k = t >> 8, d = t & 255; float s = 0.f;
        for (int e = 0; e < 256; e++) s += dW2[k * 256 + e] * swv[e * 256 + d];
        dW2v[t] = s;
    } else if (idx < 2560) {
        int t = idx - 1536; int h = t >> 8, d = t & 255; float s = sbk[d];
        for (int e = 0; e < 256; e++) s += (bias[h * 256 + e] + dB2[e]) * swk[e * 256 + d];
        dCk[t] = s;
    } else if (idx < 3584) {
        int t = idx - 2560; int h = t >> 8, d = t & 255; float s = sbv[d];
        for (int e = 0; e < 256; e++) s += (bias[h * 256 + e] + dB2[e]) * swv[e * 256 + d];
        dCv[t] = s;
    } else if (idx < 4608) {
        int t = idx - 3584; int h = t >> 8, d = t & 255; float s = sbq[d];
        for (int e = 0; e < 256; e++) s += bq[h * 256 + e] * swq[e * 256 + d];
        dBq2[t] = s;
    }
}

// ------------------------- convert / transpose -------------------------------
__global__ void cvtKn(const float4* __restrict__ s, __half2* __restrict__ o, int n4) {
    int i = blockIdx.x * 256 + threadIdx.x;
    if (i >= n4) return;
    float4 v = s[i];
    o[i * 2 + 0] = __floats2half2_rn(v.x, v.y);
    o[i * 2 + 1] = __floats2half2_rn(v.z, v.w);
}

// out[c][r] = src[r][c]; src R x C row-major, out C x R
__global__ void cvtT(const float* __restrict__ s, H* __restrict__ o, int R, int C) {
    __shared__ float t[32][33];
    int r0 = blockIdx.y * 32, c0 = blockIdx.x * 32;
    int tx = threadIdx.x & 31, ty = threadIdx.x >> 5;
    for (int y = ty; y < 32; y += 8) t[y][tx] = s[(size_t)(r0 + y) * C + c0 + tx];
    __syncthreads();
    for (int y = ty; y < 32; y += 8)
        o[(size_t)(c0 + y) * R + r0 + tx] = __float2half(t[tx][y]);
}

// three 256x256 transposes in one launch (z selects matrix)
__global__ void cvtT3(const float* __restrict__ s0, const float* __restrict__ s1,
                      const float* __restrict__ s2) {
    __shared__ float t[32][33];
    const float* s = (blockIdx.z == 0) ? s0 : (blockIdx.z == 1) ? s1 : s2;
    H* o = (blockIdx.z == 0) ? g_sqT : (blockIdx.z == 1) ? g_skT : g_svT;
    int r0 = blockIdx.y * 32, c0 = blockIdx.x * 32;
    int tx = threadIdx.x & 31, ty = threadIdx.x >> 5;
    for (int y = ty; y < 32; y += 8) t[y][tx] = s[(size_t)(r0 + y) * 256 + c0 + tx];
    __syncthreads();
    for (int y = ty; y < 32; y += 8)
        o[(size_t)(c0 + y) * 256 + r0 + tx] = __float2half(t[tx][y]);
}

// vv [(b*512+l)*1024 + h*256+d] -> vvT [((h*16+b)*256+d)*512 + l]
__global__ void transVV(const H* __restrict__ s, H* __restrict__ o) {
    __shared__ H t0[32][33];
    int l0 = blockIdx.x * 32, d0 = blockIdx.y * 32;
    int z = blockIdx.z, h = z >> 4, b = z & 15;
    int tx = threadIdx.x & 31, ty = threadIdx.x >> 5;
    for (int y = ty; y < 32; y += 8)
        t0[y][tx] = s[(size_t)(b * 512 + l0 + y) * 1024 + h * 256 + d0 + tx];
    __syncthreads();
    for (int y = ty; y < 32; y += 8)
        o[(size_t)(z * 256 + d0 + y) * 512 + l0 + tx] = t0[tx][y];
}

// ------------------------- softmax row-512: fp16 scores in, fp32+fp16 out ----
__global__ void softmax512(const __half2* __restrict__ sc, float* __restrict__ a,
                           __half2* __restrict__ ho) {
    int t = threadIdx.x;  // 128
    size_t base = (size_t)blockIdx.x * 256 + t * 2;
    __half2 h0 = sc[base], h1 = sc[base + 1];
    float4 v;
    v.x = __low2float(h0); v.y = __high2float(h0);
    v.z = __low2float(h1); v.w = __high2float(h1);
    float m = fmaxf(fmaxf(v.x, v.y), fmaxf(v.z, v.w));
#pragma unroll
    for (int o = 16; o > 0; o >>= 1) m = fmaxf(m, __shfl_xor_sync(0xffffffffu, m, o));
    __shared__ float sh[4], sh2[4];
    int w = t >> 5, lane = t & 31;
    if (lane == 0) sh[w] = m;
    __syncthreads();
    m = fmaxf(fmaxf(sh[0], sh[1]), fmaxf(sh[2], sh[3]));
    v.x = __expf(v.x - m); v.y = __expf(v.y - m); v.z = __expf(v.z - m); v.w = __expf(v.w - m);
    float s = v.x + v.y + v.z + v.w;
#pragma unroll
    for (int o = 16; o > 0; o >>= 1) s += __shfl_xor_sync(0xffffffffu, s, o);
    if (lane == 0) sh2[w] = s;
    __syncthreads();
    s = sh2[0] + sh2[1] + sh2[2] + sh2[3];
    float inv = 1.f / s;
    v.x *= inv; v.y *= inv; v.z *= inv; v.w *= inv;
    *(float4*)&a[(size_t)blockIdx.x * 512 + t * 4] = v;
    ho[base + 0] = __floats2half2_rn(v.x, v.y);
    ho[base + 1] = __floats2half2_rn(v.z, v.w);
}

// ------------------------- mma.sync fp16 GEMM, tile 128x128 ------------------
// 4 warps as 2x2, warp tile 64x64; 32-wide K-chunks; 4-stage cp.async; occ 2.
// One __syncthreads per chunk; B fragments via pairwise ldmatrix.x4.
// TBIG merges qq/kk/vv (z selects); TFOLDA merges the 3 weight folds.
// TSC emits fp16 raw scores; TTANH emits fp32 output.
template <int MODE>
__global__ __launch_bounds__(128, 2)
void gemmTC(const H* __restrict__ Ah, const H* __restrict__ A2h,
            const H* __restrict__ Bh,
            H* __restrict__ Ch, float* __restrict__ Cf,
            int K, int lda, int ldb, int ldc,
            const float* __restrict__ bias, const float* __restrict__ pa) {
    extern __shared__ H smem[];
    const int tid = threadIdx.x;
    const int lane = tid & 31, wid = tid >> 5;
    const int wm = (wid >> 1) * 64, wn = (wid & 1) * 64;
    const int bm = blockIdx.y * 128, bn = blockIdx.x * 128;
    const int z = blockIdx.z;
    int which = 0;

    if (MODE == TBIG) {
        which = z;                       // 0=qq 1=kk 2=vv
        Ah = which ? g_v : g_q;
        Bh = (which == 0) ? g_Wq2T : (which == 1) ? g_WvkT : g_WvvT;
        Ch = (which == 0) ? g_qq : (which == 1) ? g_kk : g_vv;
    }
    if (MODE == TFOLDA) {
        int head = z & 3; which = z >> 2;
        Ah = (which == 0) ? g_sqT : (which == 1) ? g_skT : g_svT;
        Bh = ((which == 0) ? g_Wq : g_Wv) + head * 256;
        Ch = ((which == 0) ? g_Wq2T : (which == 1) ? g_WvkT : g_WvvT) +
             (size_t)head * 256 * 1024;
    }
    if (MODE == TSC) {
        int h = z >> 4, b = z & 15;
        size_t o = (size_t)b * 512 * 1024 + h * 256;
        Ah += o; Bh += o;
        Ch += (size_t)z * 262144;
    }
    if (MODE == TCTX) {
        int h = z >> 4, b = z & 15;
        Ah += (size_t)z * 262144;
        Bh += (size_t)z * 131072;
        Ch += (size_t)b * 512 * 1024 + h * 256;
    }

    float acc[4][8][4];
#pragma unroll
    for (int a = 0; a < 4; a++)
#pragma unroll
        for (int b = 0; b < 8; b++)
#pragma unroll
            for (int c = 0; c < 4; c++) acc[a][b][c] = 0.f;

    const int NC = K >> 5;  // 32-wide K-chunks
    uint32_t sbase = smem_u32(smem);

    const int rowL = tid >> 2;          // 0..31
    const int segL = (tid & 3) * 8;     // half offset within 32-half row

#define ISSUE(c_) do {                                                             \
    int k0 = (c_) << 5;                                                            \
    const H* ah = Ah; int ka = k0;                                                 \
    if (MODE == TTANH && k0 >= 1024) { ah = A2h; ka = k0 - 1024; }                 \
    uint32_t st = sbase + ((c_) & 3) * STGB;                                       \
    uint32_t so = st + (rowL * 40 + segL) * 2;                                     \
    CPA16(so,        ah + (size_t)(bm + rowL) * lda + ka + segL);                  \
    CPA16(so + 2560, ah + (size_t)(bm + rowL + 32) * lda + ka + segL);             \
    CPA16(so + 5120, ah + (size_t)(bm + rowL + 64) * lda + ka + segL);             \
    CPA16(so + 7680, ah + (size_t)(bm + rowL + 96) * lda + ka + segL);             \
    uint32_t sb = st + BOFF + (rowL * 40 + segL) * 2;                              \
    CPA16(sb,        Bh + (size_t)(bn + rowL) * ldb + k0 + segL);                  \
    CPA16(sb + 2560, Bh + (size_t)(bn + rowL + 32) * ldb + k0 + segL);             \
    CPA16(sb + 5120, Bh + (size_t)(bn + rowL + 64) * ldb + k0 + segL);             \
    CPA16(sb + 7680, Bh + (size_t)(bn + rowL + 96) * ldb + k0 + segL);             \
    CPCOMMIT();                                                                    \
} while (0)

    const int la15 = lane & 15;
    const int laHi = (lane >> 4) << 3;
    const int broff = ((lane >> 4) << 3) + (lane & 7);   // B x4 row offset
    const int bcoff = ((lane >> 3) & 1) << 3;            // B x4 col offset

    ISSUE(0); ISSUE(1); ISSUE(2);
    for (int c = 0; c < NC; c++) {
        int rem = NC - 1 - c;
        if (rem >= 2) { CPWAIT2(); } else if (rem == 1) { CPWAIT1(); } else { CPWAIT0(); }
        __syncthreads();
        if (c + 3 < NC) ISSUE(c + 3);
        uint32_t st = sbase + (c & 3) * STGB;
#pragma unroll
        for (int kk = 0; kk < 2; kk++) {
            uint32_t af[4][4], bh[8][2];
#pragma unroll
            for (int mt = 0; mt < 4; mt++) {
                uint32_t addr = st + ((wm + mt * 16 + la15) * 40 + kk * 16 + laHi) * 2;
                LDSM4(af[mt][0], af[mt][1], af[mt][2], af[mt][3], addr);
            }
#pragma unroll
            for (int np = 0; np < 4; np++) {
                uint32_t addr = st + BOFF +
                    ((wn + np * 16 + broff) * 40 + kk * 16 + bcoff) * 2;
                LDSM4(bh[2 * np][0], bh[2 * np][1], bh[2 * np + 1][0], bh[2 * np + 1][1], addr);
            }
#pragma unroll
            for (int mt = 0; mt < 4; mt++)
#pragma unroll
                for (int nt = 0; nt < 8; nt++)
                    MMA16816(acc[mt][nt], af[mt], bh[nt]);
        }
    }
#undef ISSUE

    // ------------- epilogue: fused math + emit, straight from regs -----------
    const bool doKV = (MODE == TBIG) && (which != 0);
    const float* W2x = (which == 1) ? dW2k : dW2v;
    const float* cxp = (which == 1) ? dCk : dCv;
#pragma unroll
    for (int mt = 0; mt < 4; mt++) {
        int r0g = bm + wm + mt * 16 + (lane >> 2);
        int r1g = r0g + 8;
        float p0a = 0.f, p1a = 0.f, p2a = 0.f, p0b = 0.f, p1b = 0.f, p2b = 0.f;
        if (MODE == TBIG) {
            if (doKV) {
                int hh = (bn + wn) >> 8;   // 64-wide warp col inside one head
                {
                    int b = r0g >> 9, l = r0g & 511;
                    size_t pb = (size_t)(b * 4 + hh) * 512;
                    p0a = (l >= 1)   ? pa[pb + l - 1] : 0.f;
                    p1a =              pa[pb + l];
                    p2a = (l <= 510) ? pa[pb + l + 1] : 0.f;
                }
                {
                    int b = r1g >> 9, l = r1g & 511;
                    size_t pb = (size_t)(b * 4 + hh) * 512;
                    p0b = (l >= 1)   ? pa[pb + l - 1] : 0.f;
                    p1b =              pa[pb + l];
                    p2b = (l <= 510) ? pa[pb + l + 1] : 0.f;
                }
            }
        }
#pragma unroll
        for (int nt = 0; nt < 8; nt++) {
            int cc = bn + wn + nt * 8 + (lane & 3) * 2;
            float v00 = acc[mt][nt][0], v01 = acc[mt][nt][1];
            float v10 = acc[mt][nt][2], v11 = acc[mt][nt][3];
            if (MODE == TBIG) {
                if (which == 0) {
                    float b0 = dBq2[cc], b1 = dBq2[cc + 1];
                    v00 += b0; v01 += b1; v10 += b0; v11 += b1;
                } else {
                    int d0 = cc & 255, d1 = d0 + 1;
                    float c0 = cxp[cc], c1 = cxp[cc + 1];
                    float w00 = W2x[d0], w10 = W2x[256 + d0], w20 = W2x[512 + d0];
                    float w01 = W2x[d1], w11 = W2x[256 + d1], w21 = W2x[512 + d1];
                    v00 += c0 + p0a * w00 + p1a * w10 + p2a * w20;
                    v01 += c1 + p0a * w01 + p1a * w11 + p2a * w21;
                    v10 += c0 + p0b * w00 + p1b * w10 + p2b * w20;
                    v11 += c1 + p0b * w01 + p1b * w11 + p2b * w21;
                }
            }
            if (MODE == TSC) { v00 *= 0.0625f; v01 *= 0.0625f; v10 *= 0.0625f; v11 *= 0.0625f; }
            if (MODE == TTANH) {
                float b0 = bias[cc], b1 = bias[cc + 1];
                v00 = tanhf(v00 + b0); v01 = tanhf(v01 + b1);
                v10 = tanhf(v10 + b0); v11 = tanhf(v11 + b1);
                *(float2*)&Cf[(size_t)r0g * ldc + cc] = make_float2(v00, v01);
                *(float2*)&Cf[(size_t)r1g * ldc + cc] = make_float2(v10, v11);
            } else {
                *(__half2*)(Ch + (size_t)r0g * ldc + cc) = __floats2half2_rn(v00, v01);
                *(__half2*)(Ch + (size_t)r1g * ldc + cc) = __floats2half2_rn(v10, v11);
            }
        }
    }
}

// ------------------------- launch --------------------------------------------
extern "C" void kernel_launch(void* const* d_in, const int* in_sizes, int n_in,
                              void* d_out, int out_size) {
    const float* query = (const float*)d_in[0];
    const float* value = (const float*)d_in[1];
    const float* pa    = (const float*)d_in[2];
    const float* cw    = (const float*)d_in[3];
    const float* cb    = (const float*)d_in[4];
    const float* Wq    = (const float*)d_in[5];
    const float* bq    = (const float*)d_in[6];
    const float* Wv    = (const float*)d_in[7];
    const float* Wloc  = (const float*)d_in[8];
    const float* bias  = (const float*)d_in[9];
    const float* Wout  = (const float*)d_in[10];
    const float* bout  = (const float*)d_in[11];
    const float* swq   = (const float*)d_in[12];
    const float* sbq   = (const float*)d_in[13];
    const float* swk   = (const float*)d_in[14];
    const float* sbk   = (const float*)d_in[15];
    const float* swv   = (const float*)d_in[16];
    const float* sbv   = (const float*)d_in[17];

    float* out = (float*)d_out;
    const size_t OUT_ELEMS  = (size_t)16 * 512 * 1024;
    const size_t ATTN_ELEMS = (size_t)64 * 512 * 512;

    float* pATT;
    cudaGetSymbolAddress((void**)&pATT, dATTN);
#define GETH(p, sym) H* p; cudaGetSymbolAddress((void**)&p, sym)
    GETH(qh, g_q);       GETH(vh, g_v);
    GETH(Wqh, g_Wq);     GETH(Wvh, g_Wv);
    GETH(WoT, g_WoT);
    GETH(qq, g_qq);      GETH(kk, g_kk);      GETH(vv, g_vv);
    GETH(vvT, g_vvT);    GETH(sc, g_sc);      GETH(at, g_at);
    GETH(cx, g_cx);
#undef GETH

    float* attn = ((size_t)out_size >= OUT_ELEMS + ATTN_ELEMS) ? (out + OUT_ELEMS) : pATT;

    // Not stream ops; deterministic on every call (no static guards allowed).
    cudaFuncSetAttribute(gemmTC<TFOLDA>, cudaFuncAttributeMaxDynamicSharedMemorySize, SMEMDYN);
    cudaFuncSetAttribute(gemmTC<TBIG>,   cudaFuncAttributeMaxDynamicSharedMemorySize, SMEMDYN);
    cudaFuncSetAttribute(gemmTC<TSC>,    cudaFuncAttributeMaxDynamicSharedMemorySize, SMEMDYN);
    cudaFuncSetAttribute(gemmTC<TCTX>,   cudaFuncAttributeMaxDynamicSharedMemorySize, SMEMDYN);
    cudaFuncSetAttribute(gemmTC<TTANH>,  cudaFuncAttributeMaxDynamicSharedMemorySize, SMEMDYN);

    dim3 T(128);
    // precompute + fp16 converts
    prep1<<<1, 256>>>(cw, cb, Wloc);
    prep2<<<18, 256>>>(swq, sbq, swk, sbk, swv, sbv, bias, bq);
    cvtKn<<<8192, 256>>>((const float4*)query, (__half2*)qh, 2097152);
    cvtKn<<<8192, 256>>>((const float4*)value, (__half2*)vh, 2097152);
    cvtKn<<<1024, 256>>>((const float4*)Wq, (__half2*)Wqh, 262144);
    cvtKn<<<1024, 256>>>((const float4*)Wv, (__half2*)Wvh, 262144);
    cvtT3<<<dim3(8, 8, 3), 256>>>(swq, swk, swv);
    cvtT<<<dim3(32, 64), 256>>>(Wout, WoT, 2048, 1024);

    // weight folds, all 12 tiles in one launch (z: head = z&3, which = z>>2)
    gemmTC<TFOLDA><<<dim3(8, 2, 12), T, SMEMDYN>>>(0, 0, 0,
        0, 0, 256, 256, 1024, 1024, 0, 0);

    // qq / kk / vv in one launch (z selects), fused epilogues emit fp16
    gemmTC<TBIG><<<dim3(8, 64, 3), T, SMEMDYN>>>(0, 0, 0,
        0, 0, 1024, 1024, 1024, 1024, 0, pa);
    transVV<<<dim3(16, 8, 64), 256>>>(vv, vvT);

    // attention: scores emitted fp16, softmax reads fp16, writes fp32 attn + fp16
    gemmTC<TSC><<<dim3(4, 4, 64), T, SMEMDYN>>>(qq, 0, kk,
        sc, 0, 256, 1024, 1024, 512, 0, 0);
    softmax512<<<64 * 512, 128>>>((const __half2*)sc, attn, (__half2*)at);
    gemmTC<TCTX><<<dim3(2, 4, 64), T, SMEMDYN>>>(at, 0, vvT,
        cx, 0, 512, 512, 512, 1024, 0, 0);

    // out = tanh([ctx, query] @ Wout + bout)
    gemmTC<TTANH><<<dim3(8, 64, 1), T, SMEMDYN>>>(cx, qh, WoT,
        0, out, 2048, 1024, 2048, 1024, bout, 0);
}